// round 1
// baseline (speedup 1.0000x reference)
#include <cuda_runtime.h>
#include <math.h>

#define S_LEN 2048
#define T_LEN 2048
#define BATCH 2
#define EDIM  1024
#define HEADS 16
#define HDIM  64
#define HD    (HEADS*HDIM)   /* 1024 */

// ---------------- scratch (static device globals; no allocation) ----------
__device__ float g_Q [BATCH*HEADS*S_LEN*HDIM];   // (B,H,S,D)
__device__ float g_K [BATCH*HEADS*T_LEN*HDIM];   // (B,H,T,D)
__device__ float g_V [BATCH*HEADS*T_LEN*HDIM];   // (B,H,T,D)
__device__ float g_AV[S_LEN*BATCH*HD];           // (S,B,HD)

// ---------------------------------------------------------------------------
// Generic 128x128x16 fp32 SGEMM, 256 threads, 8x8 per thread.
// MODE 0: kv = enc @ Wkv + bkv  -> scatter to g_K / g_V  (N = 2048)
// MODE 1: q  = in  @ Wq  + bq + u -> scatter to g_Q      (N = 1024)
// MODE 2: out = g_AV @ Wp + bp  -> row-major d_out       (N = 1024)
// ---------------------------------------------------------------------------
template<int MODE>
__global__ __launch_bounds__(256) void sgemm_kernel(
    const float* __restrict__ A, const float* __restrict__ B,
    const float* __restrict__ bias, const float* __restrict__ u,
    float* __restrict__ out, int M, int N, int K)
{
    __shared__ float As[16][132];   // A transposed: As[k][m]
    __shared__ float Bs[16][128];   // Bs[k][n]

    const float* Ap = (MODE == 2) ? g_AV : A;

    const int tid  = threadIdx.x;
    const int m0   = blockIdx.y * 128;
    const int n0   = blockIdx.x * 128;
    const int ty   = tid >> 4,  tx = tid & 15;
    const int row0 = ty * 8,    col0 = tx * 8;

    const int aRow = tid >> 2;          // 0..63
    const int aCol = (tid & 3) * 4;     // 0,4,8,12
    const int bRow = tid >> 5;          // 0..7
    const int bCol = (tid & 31) * 4;    // 0..124

    float acc[8][8] = {};

    for (int k0 = 0; k0 < K; k0 += 16) {
        #pragma unroll
        for (int l = 0; l < 2; l++) {
            int r = aRow + l * 64;
            float4 v = *(const float4*)(Ap + (size_t)(m0 + r) * K + k0 + aCol);
            As[aCol + 0][r] = v.x;
            As[aCol + 1][r] = v.y;
            As[aCol + 2][r] = v.z;
            As[aCol + 3][r] = v.w;
        }
        #pragma unroll
        for (int l = 0; l < 2; l++) {
            int r = bRow + l * 8;
            *(float4*)&Bs[r][bCol] =
                *(const float4*)(B + (size_t)(k0 + r) * N + n0 + bCol);
        }
        __syncthreads();

        #pragma unroll
        for (int k = 0; k < 16; k++) {
            float a[8], bb[8];
            *(float4*)&a [0] = *(float4*)&As[k][row0];
            *(float4*)&a [4] = *(float4*)&As[k][row0 + 4];
            *(float4*)&bb[0] = *(float4*)&Bs[k][col0];
            *(float4*)&bb[4] = *(float4*)&Bs[k][col0 + 4];
            #pragma unroll
            for (int i = 0; i < 8; i++)
                #pragma unroll
                for (int j = 0; j < 8; j++)
                    acc[i][j] += a[i] * bb[j];
        }
        __syncthreads();
    }

    // ---------------- epilogue ----------------
    #pragma unroll
    for (int i = 0; i < 8; i++) {
        int m = m0 + row0 + i;
        int t = m >> 1;          // row index in (T or S)
        int b = m & 1;           // batch   (row = t*B + b, B == 2)
        #pragma unroll
        for (int j = 0; j < 8; j++) {
            int   n = n0 + col0 + j;
            float c = acc[i][j] + bias[n];
            if (MODE == 0) {
                if (n < HD) {
                    int h = n >> 6, d = n & 63;
                    g_K[(((size_t)(b * HEADS + h)) * T_LEN + t) * HDIM + d] = c;
                } else {
                    int nn = n - HD;
                    int h = nn >> 6, d = nn & 63;
                    g_V[(((size_t)(b * HEADS + h)) * T_LEN + t) * HDIM + d] = c;
                }
            } else if (MODE == 1) {
                int h = n >> 6, d = n & 63;
                g_Q[(((size_t)(b * HEADS + h)) * S_LEN + t) * HDIM + d] = c + u[n];
            } else {
                out[(size_t)m * EDIM + n] = c;
            }
        }
    }
}

// ---------------------------------------------------------------------------
// Flash attention (fp32, online softmax).
// grid = (S/64, B*H), 256 threads. Each CTA: 64 query rows of one (b,h),
// loops T in 64-col tiles. Thread (ty,tx) owns a 4x4 score tile and a
// 4(rows) x 4(D-cols) output tile.
//   Qs [s][d]  (64x68)
//   Kt [d][t]  (64x68)  — transposed K; reused as Pt[t][r] for the PV phase
//   Vs [t][d]  (64x68)
// ---------------------------------------------------------------------------
__global__ __launch_bounds__(256) void attn_kernel(const unsigned char* __restrict__ mask)
{
    __shared__ float Qs[64][68];
    __shared__ float Kt[64][68];
    __shared__ float Vs[64][68];

    const int bh = blockIdx.y;              // = b*HEADS + h
    const int b  = bh >> 4;
    const int h  = bh & 15;
    const int s0 = blockIdx.x * 64;
    const int tid = threadIdx.x;
    const int ty = tid >> 4, tx = tid & 15;

    const float* Qg = g_Q + (size_t)bh * S_LEN * HDIM;
    const float* Kg = g_K + (size_t)bh * T_LEN * HDIM;
    const float* Vg = g_V + (size_t)bh * T_LEN * HDIM;

    // load Q tile (row-major)
    #pragma unroll
    for (int it = 0; it < 4; it++) {
        int i = tid + it * 256;
        int r = i >> 4, c = (i & 15) * 4;
        *(float4*)&Qs[r][c] = *(const float4*)(Qg + (size_t)(s0 + r) * HDIM + c);
    }

    float o[4][4] = {};
    float mrun[4] = {-INFINITY, -INFINITY, -INFINITY, -INFINITY};
    float lrun[4] = {};

    for (int j0 = 0; j0 < T_LEN; j0 += 64) {
        __syncthreads();   // protects Kt/Vs reuse (and Qs on first iter)

        // load K (transposed into Kt[d][t]) and V (row-major)
        #pragma unroll
        for (int it = 0; it < 4; it++) {
            int i = tid + it * 256;
            int r = i >> 4, c = (i & 15) * 4;
            float4 kv = *(const float4*)(Kg + (size_t)(j0 + r) * HDIM + c);
            Kt[c + 0][r] = kv.x;
            Kt[c + 1][r] = kv.y;
            Kt[c + 2][r] = kv.z;
            Kt[c + 3][r] = kv.w;
            *(float4*)&Vs[r][c] = *(const float4*)(Vg + (size_t)(j0 + r) * HDIM + c);
        }
        __syncthreads();

        // ---- scores: s[i][j] = sum_d Q[r_i][d] * K[c_j][d] ----
        float s[4][4] = {};
        #pragma unroll 8
        for (int d = 0; d < 64; d++) {
            float4 k4 = *(float4*)&Kt[d][tx * 4];
            float q0 = Qs[ty * 4 + 0][d];
            float q1 = Qs[ty * 4 + 1][d];
            float q2 = Qs[ty * 4 + 2][d];
            float q3 = Qs[ty * 4 + 3][d];
            s[0][0] += q0 * k4.x; s[0][1] += q0 * k4.y; s[0][2] += q0 * k4.z; s[0][3] += q0 * k4.w;
            s[1][0] += q1 * k4.x; s[1][1] += q1 * k4.y; s[1][2] += q1 * k4.z; s[1][3] += q1 * k4.w;
            s[2][0] += q2 * k4.x; s[2][1] += q2 * k4.y; s[2][2] += q2 * k4.z; s[2][3] += q2 * k4.w;
            s[3][0] += q3 * k4.x; s[3][1] += q3 * k4.y; s[3][2] += q3 * k4.z; s[3][3] += q3 * k4.w;
        }

        // ---- scale + mask + online softmax ----
        #pragma unroll
        for (int i = 0; i < 4; i++) {
            int sg = s0 + ty * 4 + i;
            const unsigned char* mrow = mask + (size_t)sg * T_LEN + j0 + tx * 4;
            #pragma unroll
            for (int j = 0; j < 4; j++) {
                float v = s[i][j] * 0.125f;           // 1/sqrt(64)
                if (mrow[j]) v = -INFINITY;
                s[i][j] = v;
            }
            float mx = fmaxf(fmaxf(s[i][0], s[i][1]), fmaxf(s[i][2], s[i][3]));
            #pragma unroll
            for (int off = 8; off > 0; off >>= 1)
                mx = fmaxf(mx, __shfl_xor_sync(0xffffffffu, mx, off));
            float mnew = fmaxf(mrun[i], mx);
            float sc   = __expf(mrun[i] - mnew);
            float ps   = 0.f;
            #pragma unroll
            for (int j = 0; j < 4; j++) {
                s[i][j] = __expf(s[i][j] - mnew);
                ps += s[i][j];
            }
            #pragma unroll
            for (int off = 8; off > 0; off >>= 1)
                ps += __shfl_xor_sync(0xffffffffu, ps, off);
            lrun[i] = lrun[i] * sc + ps;
            mrun[i] = mnew;
            o[i][0] *= sc; o[i][1] *= sc; o[i][2] *= sc; o[i][3] *= sc;
        }

        // ---- write P transposed into Kt (done reading K) ----
        __syncthreads();
        #pragma unroll
        for (int i = 0; i < 4; i++)
            #pragma unroll
            for (int j = 0; j < 4; j++)
                Kt[tx * 4 + j][ty * 4 + i] = s[i][j];   // Pt[t][r]
        __syncthreads();

        // ---- PV: o[i][j] += sum_t P[r_i][t] * V[t][d_j] ----
        #pragma unroll 8
        for (int t = 0; t < 64; t++) {
            float4 v4 = *(float4*)&Vs[t][tx * 4];
            float4 p4 = *(float4*)&Kt[t][ty * 4];
            o[0][0] += p4.x * v4.x; o[0][1] += p4.x * v4.y; o[0][2] += p4.x * v4.z; o[0][3] += p4.x * v4.w;
            o[1][0] += p4.y * v4.x; o[1][1] += p4.y * v4.y; o[1][2] += p4.y * v4.z; o[1][3] += p4.y * v4.w;
            o[2][0] += p4.z * v4.x; o[2][1] += p4.z * v4.y; o[2][2] += p4.z * v4.z; o[2][3] += p4.z * v4.w;
            o[3][0] += p4.w * v4.x; o[3][1] += p4.w * v4.y; o[3][2] += p4.w * v4.z; o[3][3] += p4.w * v4.w;
        }
    }

    // ---- epilogue: normalize + store to (S,B,HD) ----
    #pragma unroll
    for (int i = 0; i < 4; i++) {
        int   sg  = s0 + ty * 4 + i;
        float inv = 1.f / lrun[i];
        float4 r4 = make_float4(o[i][0] * inv, o[i][1] * inv,
                                o[i][2] * inv, o[i][3] * inv);
        *(float4*)(g_AV + ((size_t)sg * BATCH + b) * HD + h * HDIM + tx * 4) = r4;
    }
}

// ---------------------------------------------------------------------------
extern "C" void kernel_launch(void* const* d_in, const int* in_sizes, int n_in,
                              void* d_out, int out_size)
{
    const float* inputs = (const float*)d_in[0];
    // d_in[1] pos_embedding : unused by reference
    const float* enc    = (const float*)d_in[2];
    const float* u      = (const float*)d_in[3];
    // d_in[4] v : unused by reference
    const unsigned char* mask = (const unsigned char*)d_in[5];
    const float* Wkv = (const float*)d_in[6];
    const float* bkv = (const float*)d_in[7];
    const float* Wq  = (const float*)d_in[8];
    const float* bq  = (const float*)d_in[9];
    const float* Wp  = (const float*)d_in[10];
    const float* bp  = (const float*)d_in[11];
    float* out = (float*)d_out;

    dim3 blk(256);
    // kv projection: M = T*B = 4096, N = 2048, K = 1024
    sgemm_kernel<0><<<dim3(16, 32), blk>>>(enc, Wkv, bkv, nullptr, nullptr,
                                           T_LEN * BATCH, 2 * HD, EDIM);
    // q projection (+u): M = S*B = 4096, N = 1024, K = 1024
    sgemm_kernel<1><<<dim3(8, 32), blk>>>(inputs, Wq, bq, u, nullptr,
                                          S_LEN * BATCH, HD, EDIM);
    // attention
    attn_kernel<<<dim3(S_LEN / 64, BATCH * HEADS), blk>>>(mask);
    // output projection: M = 4096, N = 1024, K = 1024
    sgemm_kernel<2><<<dim3(8, 32), blk>>>(nullptr, Wp, bp, nullptr, out,
                                          S_LEN * BATCH, HD, EDIM);
}

// round 3
// speedup vs baseline: 1.0870x; 1.0870x over previous
#include <cuda_runtime.h>
#include <math.h>
#include <stdint.h>

#define S_LEN 2048
#define T_LEN 2048
#define BATCH 2
#define EDIM  1024
#define HEADS 16
#define HDIM  64
#define HD    (HEADS*HDIM)   /* 1024 */

// ---------------- scratch (static device globals; no allocation) ----------
__device__ float g_Q [BATCH*HEADS*S_LEN*HDIM];   // (B,H,S,D)
__device__ float g_K [BATCH*HEADS*T_LEN*HDIM];   // (B,H,T,D)
__device__ float g_V [BATCH*HEADS*T_LEN*HDIM];   // (B,H,T,D)
__device__ float g_AV[S_LEN*BATCH*HD];           // (S,B,HD)

// ---------------- tf32 split helpers --------------------------------------
__device__ __forceinline__ void split_tf32(float x, uint32_t& hi, uint32_t& lo) {
    asm("cvt.rna.tf32.f32 %0, %1;" : "=r"(hi) : "f"(x));
    float l = x - __uint_as_float(hi);
    asm("cvt.rna.tf32.f32 %0, %1;" : "=r"(lo) : "f"(l));
}
__device__ __forceinline__ void mma_tf32(float* c, uint32_t a0, uint32_t a1,
                                         uint32_t a2, uint32_t a3,
                                         uint32_t b0, uint32_t b1) {
    asm volatile(
        "mma.sync.aligned.m16n8k8.row.col.f32.tf32.tf32.f32 "
        "{%0,%1,%2,%3}, {%4,%5,%6,%7}, {%8,%9}, {%0,%1,%2,%3};"
        : "+f"(c[0]), "+f"(c[1]), "+f"(c[2]), "+f"(c[3])
        : "r"(a0), "r"(a1), "r"(a2), "r"(a3), "r"(b0), "r"(b1));
}

// ===========================================================================
// 3xTF32 tensor-core GEMM: D(128x128) = A(Mx1024) @ B(1024xN) + bias
// 256 threads = 8 warps (2 m x 4 n), warp tile 64x32, mma m16n8k8.
// MODE 0: kv -> scatter g_K/g_V.  MODE 1: q (+u) -> g_Q.  MODE 2: -> out.
// ===========================================================================
template<int MODE>
__global__ __launch_bounds__(256) void mma_gemm(
    const float* __restrict__ A, const float* __restrict__ B,
    const float* __restrict__ bias, const float* __restrict__ u,
    float* __restrict__ out, int N)
{
    __shared__ float As[2][16][132];   // [buf][k][m]
    __shared__ float Bs[2][16][132];   // [buf][k][n]

    const float* Ap = (MODE == 2) ? g_AV : A;

    const int tid  = threadIdx.x;
    const int wid  = tid >> 5, lane = tid & 31;
    const int g    = lane >> 2, tg = lane & 3;     // group / thread-in-group
    const int wm   = wid >> 2,  wn = wid & 3;      // 2 x 4 warp grid
    const int m0   = blockIdx.y * 128, n0 = blockIdx.x * 128;

    const int aRow = tid >> 2;          // 0..63
    const int aCol = (tid & 3) * 4;     // 0,4,8,12
    const int bRow = tid >> 5;          // 0..7
    const int bCol = (tid & 31) * 4;    // 0..124

    float acc[4][4][4] = {};            // [mt][nt][c0..c3]

    float4 pa0, pa1, pb0, pb1;
    #define GLOAD(k0) do { \
        pa0 = *(const float4*)(Ap + (size_t)(m0 + aRow)      * 1024 + (k0) + aCol); \
        pa1 = *(const float4*)(Ap + (size_t)(m0 + aRow + 64) * 1024 + (k0) + aCol); \
        pb0 = *(const float4*)(B  + (size_t)((k0) + bRow)     * N + n0 + bCol);      \
        pb1 = *(const float4*)(B  + (size_t)((k0) + bRow + 8) * N + n0 + bCol);      \
    } while (0)
    #define SSTORE(buf) do { \
        As[buf][aCol + 0][aRow]      = pa0.x; \
        As[buf][aCol + 1][aRow]      = pa0.y; \
        As[buf][aCol + 2][aRow]      = pa0.z; \
        As[buf][aCol + 3][aRow]      = pa0.w; \
        As[buf][aCol + 0][aRow + 64] = pa1.x; \
        As[buf][aCol + 1][aRow + 64] = pa1.y; \
        As[buf][aCol + 2][aRow + 64] = pa1.z; \
        As[buf][aCol + 3][aRow + 64] = pa1.w; \
        *(float4*)&Bs[buf][bRow][bCol]     = pb0; \
        *(float4*)&Bs[buf][bRow + 8][bCol] = pb1; \
    } while (0)

    GLOAD(0);
    SSTORE(0);
    __syncthreads();

    const int NKB = 1024 / 16;   // 64 K-chunks
    for (int kb = 0; kb < NKB; kb++) {
        int buf = kb & 1;
        if (kb + 1 < NKB) GLOAD((kb + 1) * 16);

        #pragma unroll
        for (int ks = 0; ks < 16; ks += 8) {
            uint32_t ahi[4][4], alo[4][4];
            #pragma unroll
            for (int mt = 0; mt < 4; mt++) {
                int r = wm * 64 + mt * 16 + g;
                split_tf32(As[buf][ks + tg][r],         ahi[mt][0], alo[mt][0]);
                split_tf32(As[buf][ks + tg][r + 8],     ahi[mt][1], alo[mt][1]);
                split_tf32(As[buf][ks + tg + 4][r],     ahi[mt][2], alo[mt][2]);
                split_tf32(As[buf][ks + tg + 4][r + 8], ahi[mt][3], alo[mt][3]);
            }
            uint32_t bhi[4][2], blo[4][2];
            #pragma unroll
            for (int nt = 0; nt < 4; nt++) {
                int c = wn * 32 + nt * 8 + g;
                split_tf32(Bs[buf][ks + tg][c],     bhi[nt][0], blo[nt][0]);
                split_tf32(Bs[buf][ks + tg + 4][c], bhi[nt][1], blo[nt][1]);
            }
            #pragma unroll
            for (int mt = 0; mt < 4; mt++)
                #pragma unroll
                for (int nt = 0; nt < 4; nt++) {
                    float* c = acc[mt][nt];
                    mma_tf32(c, ahi[mt][0], ahi[mt][1], ahi[mt][2], ahi[mt][3],
                                bhi[nt][0], bhi[nt][1]);
                    mma_tf32(c, ahi[mt][0], ahi[mt][1], ahi[mt][2], ahi[mt][3],
                                blo[nt][0], blo[nt][1]);
                    mma_tf32(c, alo[mt][0], alo[mt][1], alo[mt][2], alo[mt][3],
                                bhi[nt][0], bhi[nt][1]);
                }
        }

        if (kb + 1 < NKB) SSTORE(1 - buf);
        __syncthreads();
    }

    // ---------------- epilogue: scatter C fragments ------------------------
    #pragma unroll
    for (int mt = 0; mt < 4; mt++) {
        #pragma unroll
        for (int nt = 0; nt < 4; nt++) {
            #pragma unroll
            for (int e = 0; e < 4; e++) {
                int m = m0 + wm * 64 + mt * 16 + g + ((e >> 1) ? 8 : 0);
                int n = n0 + wn * 32 + nt * 8 + tg * 2 + (e & 1);
                float v = acc[mt][nt][e] + __ldg(bias + n);
                int t = m >> 1, bb = m & 1;
                if (MODE == 0) {
                    if (n < HD) {
                        int h = n >> 6, d = n & 63;
                        g_K[(((size_t)(bb * HEADS + h)) * T_LEN + t) * HDIM + d] = v;
                    } else {
                        int nn = n - HD;
                        int h = nn >> 6, d = nn & 63;
                        g_V[(((size_t)(bb * HEADS + h)) * T_LEN + t) * HDIM + d] = v;
                    }
                } else if (MODE == 1) {
                    int h = n >> 6, d = n & 63;
                    g_Q[(((size_t)(bb * HEADS + h)) * S_LEN + t) * HDIM + d] =
                        v + __ldg(u + n);
                } else {
                    out[(size_t)m * EDIM + n] = v;
                }
            }
        }
    }
}

// ======================= flash attention (fp32 SIMT, unchanged) ============
__global__ __launch_bounds__(256) void attn_kernel(const unsigned char* __restrict__ mask)
{
    __shared__ float Qs[64][68];
    __shared__ float Kt[64][68];
    __shared__ float Vs[64][68];

    const int bh = blockIdx.y;
    const int b  = bh >> 4;
    const int h  = bh & 15;
    const int s0 = blockIdx.x * 64;
    const int tid = threadIdx.x;
    const int ty = tid >> 4, tx = tid & 15;

    const float* Qg = g_Q + (size_t)bh * S_LEN * HDIM;
    const float* Kg = g_K + (size_t)bh * T_LEN * HDIM;
    const float* Vg = g_V + (size_t)bh * T_LEN * HDIM;

    #pragma unroll
    for (int it = 0; it < 4; it++) {
        int i = tid + it * 256;
        int r = i >> 4, c = (i & 15) * 4;
        *(float4*)&Qs[r][c] = *(const float4*)(Qg + (size_t)(s0 + r) * HDIM + c);
    }

    float o[4][4] = {};
    float mrun[4] = {-INFINITY, -INFINITY, -INFINITY, -INFINITY};
    float lrun[4] = {};

    for (int j0 = 0; j0 < T_LEN; j0 += 64) {
        __syncthreads();
        #pragma unroll
        for (int it = 0; it < 4; it++) {
            int i = tid + it * 256;
            int r = i >> 4, c = (i & 15) * 4;
            float4 kv = *(const float4*)(Kg + (size_t)(j0 + r) * HDIM + c);
            Kt[c + 0][r] = kv.x;
            Kt[c + 1][r] = kv.y;
            Kt[c + 2][r] = kv.z;
            Kt[c + 3][r] = kv.w;
            *(float4*)&Vs[r][c] = *(const float4*)(Vg + (size_t)(j0 + r) * HDIM + c);
        }
        __syncthreads();

        float s[4][4] = {};
        #pragma unroll 8
        for (int d = 0; d < 64; d++) {
            float4 k4 = *(float4*)&Kt[d][tx * 4];
            float q0 = Qs[ty * 4 + 0][d];
            float q1 = Qs[ty * 4 + 1][d];
            float q2 = Qs[ty * 4 + 2][d];
            float q3 = Qs[ty * 4 + 3][d];
            s[0][0] += q0 * k4.x; s[0][1] += q0 * k4.y; s[0][2] += q0 * k4.z; s[0][3] += q0 * k4.w;
            s[1][0] += q1 * k4.x; s[1][1] += q1 * k4.y; s[1][2] += q1 * k4.z; s[1][3] += q1 * k4.w;
            s[2][0] += q2 * k4.x; s[2][1] += q2 * k4.y; s[2][2] += q2 * k4.z; s[2][3] += q2 * k4.w;
            s[3][0] += q3 * k4.x; s[3][1] += q3 * k4.y; s[3][2] += q3 * k4.z; s[3][3] += q3 * k4.w;
        }

        #pragma unroll
        for (int i = 0; i < 4; i++) {
            int sg = s0 + ty * 4 + i;
            const unsigned char* mrow = mask + (size_t)sg * T_LEN + j0 + tx * 4;
            #pragma unroll
            for (int j = 0; j < 4; j++) {
                float v = s[i][j] * 0.125f;
                if (mrow[j]) v = -INFINITY;
                s[i][j] = v;
            }
            float mx = fmaxf(fmaxf(s[i][0], s[i][1]), fmaxf(s[i][2], s[i][3]));
            #pragma unroll
            for (int off = 8; off > 0; off >>= 1)
                mx = fmaxf(mx, __shfl_xor_sync(0xffffffffu, mx, off));
            float mnew = fmaxf(mrun[i], mx);
            float sc   = __expf(mrun[i] - mnew);
            float ps   = 0.f;
            #pragma unroll
            for (int j = 0; j < 4; j++) {
                s[i][j] = __expf(s[i][j] - mnew);
                ps += s[i][j];
            }
            #pragma unroll
            for (int off = 8; off > 0; off >>= 1)
                ps += __shfl_xor_sync(0xffffffffu, ps, off);
            lrun[i] = lrun[i] * sc + ps;
            mrun[i] = mnew;
            o[i][0] *= sc; o[i][1] *= sc; o[i][2] *= sc; o[i][3] *= sc;
        }

        __syncthreads();
        #pragma unroll
        for (int i = 0; i < 4; i++)
            #pragma unroll
            for (int j = 0; j < 4; j++)
                Kt[tx * 4 + j][ty * 4 + i] = s[i][j];
        __syncthreads();

        #pragma unroll 8
        for (int t = 0; t < 64; t++) {
            float4 v4 = *(float4*)&Vs[t][tx * 4];
            float4 p4 = *(float4*)&Kt[t][ty * 4];
            o[0][0] += p4.x * v4.x; o[0][1] += p4.x * v4.y; o[0][2] += p4.x * v4.z; o[0][3] += p4.x * v4.w;
            o[1][0] += p4.y * v4.x; o[1][1] += p4.y * v4.y; o[1][2] += p4.y * v4.z; o[1][3] += p4.y * v4.w;
            o[2][0] += p4.z * v4.x; o[2][1] += p4.z * v4.y; o[2][2] += p4.z * v4.z; o[2][3] += p4.z * v4.w;
            o[3][0] += p4.w * v4.x; o[3][1] += p4.w * v4.y; o[3][2] += p4.w * v4.z; o[3][3] += p4.w * v4.w;
        }
    }

    #pragma unroll
    for (int i = 0; i < 4; i++) {
        int   sg  = s0 + ty * 4 + i;
        float inv = 1.f / lrun[i];
        float4 r4 = make_float4(o[i][0] * inv, o[i][1] * inv,
                                o[i][2] * inv, o[i][3] * inv);
        *(float4*)(g_AV + ((size_t)sg * BATCH + b) * HD + h * HDIM + tx * 4) = r4;
    }
}

// ---------------------------------------------------------------------------
extern "C" void kernel_launch(void* const* d_in, const int* in_sizes, int n_in,
                              void* d_out, int out_size)
{
    const float* inputs = (const float*)d_in[0];
    const float* enc    = (const float*)d_in[2];
    const float* u      = (const float*)d_in[3];
    const unsigned char* mask = (const unsigned char*)d_in[5];
    const float* Wkv = (const float*)d_in[6];
    const float* bkv = (const float*)d_in[7];
    const float* Wq  = (const float*)d_in[8];
    const float* bq  = (const float*)d_in[9];
    const float* Wp  = (const float*)d_in[10];
    const float* bp  = (const float*)d_in[11];
    float* out = (float*)d_out;

    dim3 blk(256);
    // kv: M = 4096, N = 2048
    mma_gemm<0><<<dim3(16, 32), blk>>>(enc,    Wkv, bkv, nullptr, nullptr, 2 * HD);
    // q (+u): M = 4096, N = 1024
    mma_gemm<1><<<dim3(8, 32),  blk>>>(inputs, Wq,  bq,  u,       nullptr, HD);
    // attention
    attn_kernel<<<dim3(S_LEN / 64, BATCH * HEADS), blk>>>(mask);
    // out: M = 4096, N = 1024
    mma_gemm<2><<<dim3(8, 32),  blk>>>(nullptr, Wp,  bp,  nullptr, out,    HD);
}

// round 4
// speedup vs baseline: 1.0895x; 1.0022x over previous
#include <cuda_runtime.h>
#include <math.h>
#include <stdint.h>

#define S_LEN 2048
#define T_LEN 2048
#define BATCH 2
#define EDIM  1024
#define HEADS 16
#define HDIM  64
#define HD    (HEADS*HDIM)   /* 1024 */

// ---------------- scratch (static device globals; no allocation) ----------
__device__ float g_Q [BATCH*HEADS*S_LEN*HDIM];   // (B,H,S,D)
__device__ float g_K [BATCH*HEADS*T_LEN*HDIM];   // (B,H,T,D)
__device__ float g_V [BATCH*HEADS*T_LEN*HDIM];   // (B,H,T,D)
__device__ float g_AV[S_LEN*BATCH*HD];           // (S,B,HD)

// ---------------- tf32 split helpers --------------------------------------
__device__ __forceinline__ void split_tf32(float x, uint32_t& hi, uint32_t& lo) {
    asm("cvt.rna.tf32.f32 %0, %1;" : "=r"(hi) : "f"(x));
    float l = x - __uint_as_float(hi);
    asm("cvt.rna.tf32.f32 %0, %1;" : "=r"(lo) : "f"(l));
}
__device__ __forceinline__ void mma_tf32(float* c, uint32_t a0, uint32_t a1,
                                         uint32_t a2, uint32_t a3,
                                         uint32_t b0, uint32_t b1) {
    asm volatile(
        "mma.sync.aligned.m16n8k8.row.col.f32.tf32.tf32.f32 "
        "{%0,%1,%2,%3}, {%4,%5,%6,%7}, {%8,%9}, {%0,%1,%2,%3};"
        : "+f"(c[0]), "+f"(c[1]), "+f"(c[2]), "+f"(c[3])
        : "r"(a0), "r"(a1), "r"(a2), "r"(a3), "r"(b0), "r"(b1));
}

// ===========================================================================
// 3xTF32 tensor-core GEMM: D(128x128) = A(Mx1024) @ B(1024xN) + bias
// 256 threads = 8 warps (2 m x 4 n), warp tile 64x32, mma m16n8k8.
// MODE 0: kv -> scatter g_K/g_V.  MODE 1: q (+u) -> g_Q.  MODE 2: -> out.
// ===========================================================================
template<int MODE>
__global__ __launch_bounds__(256) void mma_gemm(
    const float* __restrict__ A, const float* __restrict__ B,
    const float* __restrict__ bias, const float* __restrict__ u,
    float* __restrict__ out, int N)
{
    __shared__ float As[2][16][132];   // [buf][k][m]
    __shared__ float Bs[2][16][132];   // [buf][k][n]

    const float* Ap = (MODE == 2) ? g_AV : A;

    const int tid  = threadIdx.x;
    const int wid  = tid >> 5, lane = tid & 31;
    const int g    = lane >> 2, tg = lane & 3;     // group / thread-in-group
    const int wm   = wid >> 2,  wn = wid & 3;      // 2 x 4 warp grid
    const int m0   = blockIdx.y * 128, n0 = blockIdx.x * 128;

    const int aRow = tid >> 2;          // 0..63
    const int aCol = (tid & 3) * 4;     // 0,4,8,12
    const int bRow = tid >> 5;          // 0..7
    const int bCol = (tid & 31) * 4;    // 0..124

    float acc[4][4][4] = {};            // [mt][nt][c0..c3]

    float4 pa0, pa1, pb0, pb1;
    #define GLOAD(k0) do { \
        pa0 = *(const float4*)(Ap + (size_t)(m0 + aRow)      * 1024 + (k0) + aCol); \
        pa1 = *(const float4*)(Ap + (size_t)(m0 + aRow + 64) * 1024 + (k0) + aCol); \
        pb0 = *(const float4*)(B  + (size_t)((k0) + bRow)     * N + n0 + bCol);      \
        pb1 = *(const float4*)(B  + (size_t)((k0) + bRow + 8) * N + n0 + bCol);      \
    } while (0)
    #define SSTORE(buf) do { \
        As[buf][aCol + 0][aRow]      = pa0.x; \
        As[buf][aCol + 1][aRow]      = pa0.y; \
        As[buf][aCol + 2][aRow]      = pa0.z; \
        As[buf][aCol + 3][aRow]      = pa0.w; \
        As[buf][aCol + 0][aRow + 64] = pa1.x; \
        As[buf][aCol + 1][aRow + 64] = pa1.y; \
        As[buf][aCol + 2][aRow + 64] = pa1.z; \
        As[buf][aCol + 3][aRow + 64] = pa1.w; \
        *(float4*)&Bs[buf][bRow][bCol]     = pb0; \
        *(float4*)&Bs[buf][bRow + 8][bCol] = pb1; \
    } while (0)

    GLOAD(0);
    SSTORE(0);
    __syncthreads();

    const int NKB = 1024 / 16;   // 64 K-chunks
    for (int kb = 0; kb < NKB; kb++) {
        int buf = kb & 1;
        if (kb + 1 < NKB) GLOAD((kb + 1) * 16);

        #pragma unroll
        for (int ks = 0; ks < 16; ks += 8) {
            uint32_t ahi[4][4], alo[4][4];
            #pragma unroll
            for (int mt = 0; mt < 4; mt++) {
                int r = wm * 64 + mt * 16 + g;
                split_tf32(As[buf][ks + tg][r],         ahi[mt][0], alo[mt][0]);
                split_tf32(As[buf][ks + tg][r + 8],     ahi[mt][1], alo[mt][1]);
                split_tf32(As[buf][ks + tg + 4][r],     ahi[mt][2], alo[mt][2]);
                split_tf32(As[buf][ks + tg + 4][r + 8], ahi[mt][3], alo[mt][3]);
            }
            uint32_t bhi[4][2], blo[4][2];
            #pragma unroll
            for (int nt = 0; nt < 4; nt++) {
                int c = wn * 32 + nt * 8 + g;
                split_tf32(Bs[buf][ks + tg][c],     bhi[nt][0], blo[nt][0]);
                split_tf32(Bs[buf][ks + tg + 4][c], bhi[nt][1], blo[nt][1]);
            }
            #pragma unroll
            for (int mt = 0; mt < 4; mt++)
                #pragma unroll
                for (int nt = 0; nt < 4; nt++) {
                    float* c = acc[mt][nt];
                    mma_tf32(c, ahi[mt][0], ahi[mt][1], ahi[mt][2], ahi[mt][3],
                                bhi[nt][0], bhi[nt][1]);
                    mma_tf32(c, ahi[mt][0], ahi[mt][1], ahi[mt][2], ahi[mt][3],
                                blo[nt][0], blo[nt][1]);
                    mma_tf32(c, alo[mt][0], alo[mt][1], alo[mt][2], alo[mt][3],
                                bhi[nt][0], bhi[nt][1]);
                }
        }

        if (kb + 1 < NKB) SSTORE(1 - buf);
        __syncthreads();
    }

    // ---------------- epilogue: scatter C fragments ------------------------
    #pragma unroll
    for (int mt = 0; mt < 4; mt++) {
        #pragma unroll
        for (int nt = 0; nt < 4; nt++) {
            #pragma unroll
            for (int e = 0; e < 4; e++) {
                int m = m0 + wm * 64 + mt * 16 + g + ((e >> 1) ? 8 : 0);
                int n = n0 + wn * 32 + nt * 8 + tg * 2 + (e & 1);
                float v = acc[mt][nt][e] + __ldg(bias + n);
                int t = m >> 1, bb = m & 1;
                if (MODE == 0) {
                    if (n < HD) {
                        int h = n >> 6, d = n & 63;
                        g_K[(((size_t)(bb * HEADS + h)) * T_LEN + t) * HDIM + d] = v;
                    } else {
                        int nn = n - HD;
                        int h = nn >> 6, d = nn & 63;
                        g_V[(((size_t)(bb * HEADS + h)) * T_LEN + t) * HDIM + d] = v;
                    }
                } else if (MODE == 1) {
                    int h = n >> 6, d = n & 63;
                    g_Q[(((size_t)(bb * HEADS + h)) * S_LEN + t) * HDIM + d] =
                        v + __ldg(u + n);
                } else {
                    out[(size_t)m * EDIM + n] = v;
                }
            }
        }
    }
}

// ======================= flash attention (fp32 SIMT, unchanged) ============
__global__ __launch_bounds__(256) void attn_kernel(const unsigned char* __restrict__ mask)
{
    __shared__ float Qs[64][68];
    __shared__ float Kt[64][68];
    __shared__ float Vs[64][68];

    const int bh = blockIdx.y;
    const int b  = bh >> 4;
    const int h  = bh & 15;
    const int s0 = blockIdx.x * 64;
    const int tid = threadIdx.x;
    const int ty = tid >> 4, tx = tid & 15;

    const float* Qg = g_Q + (size_t)bh * S_LEN * HDIM;
    const float* Kg = g_K + (size_t)bh * T_LEN * HDIM;
    const float* Vg = g_V + (size_t)bh * T_LEN * HDIM;

    #pragma unroll
    for (int it = 0; it < 4; it++) {
        int i = tid + it * 256;
        int r = i >> 4, c = (i & 15) * 4;
        *(float4*)&Qs[r][c] = *(const float4*)(Qg + (size_t)(s0 + r) * HDIM + c);
    }

    float o[4][4] = {};
    float mrun[4] = {-INFINITY, -INFINITY, -INFINITY, -INFINITY};
    float lrun[4] = {};

    for (int j0 = 0; j0 < T_LEN; j0 += 64) {
        __syncthreads();
        #pragma unroll
        for (int it = 0; it < 4; it++) {
            int i = tid + it * 256;
            int r = i >> 4, c = (i & 15) * 4;
            float4 kv = *(const float4*)(Kg + (size_t)(j0 + r) * HDIM + c);
            Kt[c + 0][r] = kv.x;
            Kt[c + 1][r] = kv.y;
            Kt[c + 2][r] = kv.z;
            Kt[c + 3][r] = kv.w;
            *(float4*)&Vs[r][c] = *(const float4*)(Vg + (size_t)(j0 + r) * HDIM + c);
        }
        __syncthreads();

        float s[4][4] = {};
        #pragma unroll 8
        for (int d = 0; d < 64; d++) {
            float4 k4 = *(float4*)&Kt[d][tx * 4];
            float q0 = Qs[ty * 4 + 0][d];
            float q1 = Qs[ty * 4 + 1][d];
            float q2 = Qs[ty * 4 + 2][d];
            float q3 = Qs[ty * 4 + 3][d];
            s[0][0] += q0 * k4.x; s[0][1] += q0 * k4.y; s[0][2] += q0 * k4.z; s[0][3] += q0 * k4.w;
            s[1][0] += q1 * k4.x; s[1][1] += q1 * k4.y; s[1][2] += q1 * k4.z; s[1][3] += q1 * k4.w;
            s[2][0] += q2 * k4.x; s[2][1] += q2 * k4.y; s[2][2] += q2 * k4.z; s[2][3] += q2 * k4.w;
            s[3][0] += q3 * k4.x; s[3][1] += q3 * k4.y; s[3][2] += q3 * k4.z; s[3][3] += q3 * k4.w;
        }

        #pragma unroll
        for (int i = 0; i < 4; i++) {
            int sg = s0 + ty * 4 + i;
            const unsigned char* mrow = mask + (size_t)sg * T_LEN + j0 + tx * 4;
            #pragma unroll
            for (int j = 0; j < 4; j++) {
                float v = s[i][j] * 0.125f;
                if (mrow[j]) v = -INFINITY;
                s[i][j] = v;
            }
            float mx = fmaxf(fmaxf(s[i][0], s[i][1]), fmaxf(s[i][2], s[i][3]));
            #pragma unroll
            for (int off = 8; off > 0; off >>= 1)
                mx = fmaxf(mx, __shfl_xor_sync(0xffffffffu, mx, off));
            float mnew = fmaxf(mrun[i], mx);
            float sc   = __expf(mrun[i] - mnew);
            float ps   = 0.f;
            #pragma unroll
            for (int j = 0; j < 4; j++) {
                s[i][j] = __expf(s[i][j] - mnew);
                ps += s[i][j];
            }
            #pragma unroll
            for (int off = 8; off > 0; off >>= 1)
                ps += __shfl_xor_sync(0xffffffffu, ps, off);
            lrun[i] = lrun[i] * sc + ps;
            mrun[i] = mnew;
            o[i][0] *= sc; o[i][1] *= sc; o[i][2] *= sc; o[i][3] *= sc;
        }

        __syncthreads();
        #pragma unroll
        for (int i = 0; i < 4; i++)
            #pragma unroll
            for (int j = 0; j < 4; j++)
                Kt[tx * 4 + j][ty * 4 + i] = s[i][j];
        __syncthreads();

        #pragma unroll 8
        for (int t = 0; t < 64; t++) {
            float4 v4 = *(float4*)&Vs[t][tx * 4];
            float4 p4 = *(float4*)&Kt[t][ty * 4];
            o[0][0] += p4.x * v4.x; o[0][1] += p4.x * v4.y; o[0][2] += p4.x * v4.z; o[0][3] += p4.x * v4.w;
            o[1][0] += p4.y * v4.x; o[1][1] += p4.y * v4.y; o[1][2] += p4.y * v4.z; o[1][3] += p4.y * v4.w;
            o[2][0] += p4.z * v4.x; o[2][1] += p4.z * v4.y; o[2][2] += p4.z * v4.z; o[2][3] += p4.z * v4.w;
            o[3][0] += p4.w * v4.x; o[3][1] += p4.w * v4.y; o[3][2] += p4.w * v4.z; o[3][3] += p4.w * v4.w;
        }
    }

    #pragma unroll
    for (int i = 0; i < 4; i++) {
        int   sg  = s0 + ty * 4 + i;
        float inv = 1.f / lrun[i];
        float4 r4 = make_float4(o[i][0] * inv, o[i][1] * inv,
                                o[i][2] * inv, o[i][3] * inv);
        *(float4*)(g_AV + ((size_t)sg * BATCH + b) * HD + h * HDIM + tx * 4) = r4;
    }
}

// ---------------------------------------------------------------------------
extern "C" void kernel_launch(void* const* d_in, const int* in_sizes, int n_in,
                              void* d_out, int out_size)
{
    const float* inputs = (const float*)d_in[0];
    const float* enc    = (const float*)d_in[2];
    const float* u      = (const float*)d_in[3];
    const unsigned char* mask = (const unsigned char*)d_in[5];
    const float* Wkv = (const float*)d_in[6];
    const float* bkv = (const float*)d_in[7];
    const float* Wq  = (const float*)d_in[8];
    const float* bq  = (const float*)d_in[9];
    const float* Wp  = (const float*)d_in[10];
    const float* bp  = (const float*)d_in[11];
    float* out = (float*)d_out;

    dim3 blk(256);
    // kv: M = 4096, N = 2048
    mma_gemm<0><<<dim3(16, 32), blk>>>(enc,    Wkv, bkv, nullptr, nullptr, 2 * HD);
    // q (+u): M = 4096, N = 1024
    mma_gemm<1><<<dim3(8, 32),  blk>>>(inputs, Wq,  bq,  u,       nullptr, HD);
    // attention
    attn_kernel<<<dim3(S_LEN / 64, BATCH * HEADS), blk>>>(mask);
    // out: M = 4096, N = 1024
    mma_gemm<2><<<dim3(8, 32),  blk>>>(nullptr, Wp,  bp,  nullptr, out,    HD);
}

// round 5
// speedup vs baseline: 1.2101x; 1.1107x over previous
#include <cuda_runtime.h>
#include <math.h>
#include <stdint.h>

#define S_LEN 2048
#define T_LEN 2048
#define BATCH 2
#define EDIM  1024
#define HEADS 16
#define HDIM  64
#define HD    (HEADS*HDIM)   /* 1024 */

// ---------------- scratch (static device globals; no allocation) ----------
__device__ float g_Q [BATCH*HEADS*S_LEN*HDIM];   // (B,H,S,D)
__device__ float g_K [BATCH*HEADS*T_LEN*HDIM];   // (B,H,T,D)
__device__ float g_V [BATCH*HEADS*T_LEN*HDIM];   // (B,H,T,D)
__device__ float g_AV[S_LEN*BATCH*HD];           // (S,B,HD)

// ---------------- tf32 split helpers --------------------------------------
__device__ __forceinline__ void split_tf32(float x, uint32_t& hi, uint32_t& lo) {
    asm("cvt.rna.tf32.f32 %0, %1;" : "=r"(hi) : "f"(x));
    float l = x - __uint_as_float(hi);
    asm("cvt.rna.tf32.f32 %0, %1;" : "=r"(lo) : "f"(l));
}
__device__ __forceinline__ uint32_t tf32_1(float x) {
    uint32_t r;
    asm("cvt.rna.tf32.f32 %0, %1;" : "=r"(r) : "f"(x));
    return r;
}
__device__ __forceinline__ void mma_tf32(float* c, uint32_t a0, uint32_t a1,
                                         uint32_t a2, uint32_t a3,
                                         uint32_t b0, uint32_t b1) {
    asm volatile(
        "mma.sync.aligned.m16n8k8.row.col.f32.tf32.tf32.f32 "
        "{%0,%1,%2,%3}, {%4,%5,%6,%7}, {%8,%9}, {%0,%1,%2,%3};"
        : "+f"(c[0]), "+f"(c[1]), "+f"(c[2]), "+f"(c[3])
        : "r"(a0), "r"(a1), "r"(a2), "r"(a3), "r"(b0), "r"(b1));
}

// ===========================================================================
// 3xTF32 tensor-core GEMM: D(128x128) = A(Mx1024) @ B(1024xN) + bias
// (unchanged from R3 — known good)
// ===========================================================================
template<int MODE>
__global__ __launch_bounds__(256) void mma_gemm(
    const float* __restrict__ A, const float* __restrict__ B,
    const float* __restrict__ bias, const float* __restrict__ u,
    float* __restrict__ out, int N)
{
    __shared__ float As[2][16][132];   // [buf][k][m]
    __shared__ float Bs[2][16][132];   // [buf][k][n]

    const float* Ap = (MODE == 2) ? g_AV : A;

    const int tid  = threadIdx.x;
    const int wid  = tid >> 5, lane = tid & 31;
    const int g    = lane >> 2, tg = lane & 3;
    const int wm   = wid >> 2,  wn = wid & 3;
    const int m0   = blockIdx.y * 128, n0 = blockIdx.x * 128;

    const int aRow = tid >> 2;
    const int aCol = (tid & 3) * 4;
    const int bRow = tid >> 5;
    const int bCol = (tid & 31) * 4;

    float acc[4][4][4] = {};

    float4 pa0, pa1, pb0, pb1;
    #define GLOAD(k0) do { \
        pa0 = *(const float4*)(Ap + (size_t)(m0 + aRow)      * 1024 + (k0) + aCol); \
        pa1 = *(const float4*)(Ap + (size_t)(m0 + aRow + 64) * 1024 + (k0) + aCol); \
        pb0 = *(const float4*)(B  + (size_t)((k0) + bRow)     * N + n0 + bCol);      \
        pb1 = *(const float4*)(B  + (size_t)((k0) + bRow + 8) * N + n0 + bCol);      \
    } while (0)
    #define SSTORE(buf) do { \
        As[buf][aCol + 0][aRow]      = pa0.x; \
        As[buf][aCol + 1][aRow]      = pa0.y; \
        As[buf][aCol + 2][aRow]      = pa0.z; \
        As[buf][aCol + 3][aRow]      = pa0.w; \
        As[buf][aCol + 0][aRow + 64] = pa1.x; \
        As[buf][aCol + 1][aRow + 64] = pa1.y; \
        As[buf][aCol + 2][aRow + 64] = pa1.z; \
        As[buf][aCol + 3][aRow + 64] = pa1.w; \
        *(float4*)&Bs[buf][bRow][bCol]     = pb0; \
        *(float4*)&Bs[buf][bRow + 8][bCol] = pb1; \
    } while (0)

    GLOAD(0);
    SSTORE(0);
    __syncthreads();

    const int NKB = 1024 / 16;
    for (int kb = 0; kb < NKB; kb++) {
        int buf = kb & 1;
        if (kb + 1 < NKB) GLOAD((kb + 1) * 16);

        #pragma unroll
        for (int ks = 0; ks < 16; ks += 8) {
            uint32_t ahi[4][4], alo[4][4];
            #pragma unroll
            for (int mt = 0; mt < 4; mt++) {
                int r = wm * 64 + mt * 16 + g;
                split_tf32(As[buf][ks + tg][r],         ahi[mt][0], alo[mt][0]);
                split_tf32(As[buf][ks + tg][r + 8],     ahi[mt][1], alo[mt][1]);
                split_tf32(As[buf][ks + tg + 4][r],     ahi[mt][2], alo[mt][2]);
                split_tf32(As[buf][ks + tg + 4][r + 8], ahi[mt][3], alo[mt][3]);
            }
            uint32_t bhi[4][2], blo[4][2];
            #pragma unroll
            for (int nt = 0; nt < 4; nt++) {
                int c = wn * 32 + nt * 8 + g;
                split_tf32(Bs[buf][ks + tg][c],     bhi[nt][0], blo[nt][0]);
                split_tf32(Bs[buf][ks + tg + 4][c], bhi[nt][1], blo[nt][1]);
            }
            #pragma unroll
            for (int mt = 0; mt < 4; mt++)
                #pragma unroll
                for (int nt = 0; nt < 4; nt++) {
                    float* c = acc[mt][nt];
                    mma_tf32(c, ahi[mt][0], ahi[mt][1], ahi[mt][2], ahi[mt][3],
                                bhi[nt][0], bhi[nt][1]);
                    mma_tf32(c, ahi[mt][0], ahi[mt][1], ahi[mt][2], ahi[mt][3],
                                blo[nt][0], blo[nt][1]);
                    mma_tf32(c, alo[mt][0], alo[mt][1], alo[mt][2], alo[mt][3],
                                bhi[nt][0], bhi[nt][1]);
                }
        }

        if (kb + 1 < NKB) SSTORE(1 - buf);
        __syncthreads();
    }

    #pragma unroll
    for (int mt = 0; mt < 4; mt++) {
        #pragma unroll
        for (int nt = 0; nt < 4; nt++) {
            #pragma unroll
            for (int e = 0; e < 4; e++) {
                int m = m0 + wm * 64 + mt * 16 + g + ((e >> 1) ? 8 : 0);
                int n = n0 + wn * 32 + nt * 8 + tg * 2 + (e & 1);
                float v = acc[mt][nt][e] + __ldg(bias + n);
                int t = m >> 1, bb = m & 1;
                if (MODE == 0) {
                    if (n < HD) {
                        int h = n >> 6, d = n & 63;
                        g_K[(((size_t)(bb * HEADS + h)) * T_LEN + t) * HDIM + d] = v;
                    } else {
                        int nn = n - HD;
                        int h = nn >> 6, d = nn & 63;
                        g_V[(((size_t)(bb * HEADS + h)) * T_LEN + t) * HDIM + d] = v;
                    }
                } else if (MODE == 1) {
                    int h = n >> 6, d = n & 63;
                    g_Q[(((size_t)(bb * HEADS + h)) * S_LEN + t) * HDIM + d] =
                        v + __ldg(u + n);
                } else {
                    out[(size_t)m * EDIM + n] = v;
                }
            }
        }
    }
}

// ===========================================================================
// Tensor-core flash attention, 3xTF32.
// CTA: 128 S-rows of one (b,h). 8 warps, warp = 16 rows x full width.
// T-tile = 64. smem: Qh/Ql[128][68], Kh/Kl[64][68] (d-major), Vh/Vl[64][68],
// Ps[128][68]. 174KB -> 1 CTA/SM.
// ===========================================================================
#define PADW 68

__global__ __launch_bounds__(256) void attn_mma(const unsigned char* __restrict__ mask)
{
    extern __shared__ float sm[];
    float* Qh = sm;                    // [128][68]
    float* Ql = Qh + 128 * PADW;
    float* Kh = Ql + 128 * PADW;       // [d=64][t=68]
    float* Kl = Kh + 64 * PADW;
    float* Vh = Kl + 64 * PADW;        // [t=64][d=68]
    float* Vl = Vh + 64 * PADW;
    float* Ps = Vl + 64 * PADW;        // [128][68]

    const int bh = blockIdx.y;
    const int b  = bh >> 4;
    const int h  = bh & 15;
    const int s0 = blockIdx.x * 128;
    const int tid = threadIdx.x;
    const int wid = tid >> 5, lane = tid & 31;
    const int g   = lane >> 2, tg = lane & 3;
    const int rowA = wid * 16 + g;     // local row of fragment row 0 (row 1 = +8)

    const float* Qg = g_Q + (size_t)bh * S_LEN * HDIM;
    const float* Kg = g_K + (size_t)bh * T_LEN * HDIM;
    const float* Vg = g_V + (size_t)bh * T_LEN * HDIM;

    // ---- load + split Q once ----
    #pragma unroll
    for (int it = 0; it < 8; it++) {
        int idx = tid + it * 256;
        int r = idx >> 4, c = (idx & 15) * 4;
        float4 q = *(const float4*)(Qg + (size_t)(s0 + r) * HDIM + c);
        uint32_t hx, lx, hy, ly, hz, lz, hw, lw;
        split_tf32(q.x, hx, lx); split_tf32(q.y, hy, ly);
        split_tf32(q.z, hz, lz); split_tf32(q.w, hw, lw);
        *(float4*)&Qh[r * PADW + c] = make_float4(__uint_as_float(hx), __uint_as_float(hy),
                                                  __uint_as_float(hz), __uint_as_float(hw));
        *(float4*)&Ql[r * PADW + c] = make_float4(__uint_as_float(lx), __uint_as_float(ly),
                                                  __uint_as_float(lz), __uint_as_float(lw));
    }

    float o[8][4] = {};
    float m0 = -1e30f, m1 = -1e30f, l0 = 0.f, l1 = 0.f;

    for (int j0 = 0; j0 < T_LEN; j0 += 64) {
        __syncthreads();
        // ---- load + split K (transposed) and V; OR-scan mask tile ----
        uint32_t mor = 0;
        #pragma unroll
        for (int it = 0; it < 4; it++) {
            int idx = tid + it * 256;
            int r = idx >> 4, c = (idx & 15) * 4;
            float4 k = *(const float4*)(Kg + (size_t)(j0 + r) * HDIM + c);
            uint32_t hi, lo;
            split_tf32(k.x, hi, lo); Kh[(c + 0) * PADW + r] = __uint_as_float(hi); Kl[(c + 0) * PADW + r] = __uint_as_float(lo);
            split_tf32(k.y, hi, lo); Kh[(c + 1) * PADW + r] = __uint_as_float(hi); Kl[(c + 1) * PADW + r] = __uint_as_float(lo);
            split_tf32(k.z, hi, lo); Kh[(c + 2) * PADW + r] = __uint_as_float(hi); Kl[(c + 2) * PADW + r] = __uint_as_float(lo);
            split_tf32(k.w, hi, lo); Kh[(c + 3) * PADW + r] = __uint_as_float(hi); Kl[(c + 3) * PADW + r] = __uint_as_float(lo);
            float4 v = *(const float4*)(Vg + (size_t)(j0 + r) * HDIM + c);
            uint32_t hx, lx, hy, ly, hz, lz, hw, lw;
            split_tf32(v.x, hx, lx); split_tf32(v.y, hy, ly);
            split_tf32(v.z, hz, lz); split_tf32(v.w, hw, lw);
            *(float4*)&Vh[r * PADW + c] = make_float4(__uint_as_float(hx), __uint_as_float(hy),
                                                      __uint_as_float(hz), __uint_as_float(hw));
            *(float4*)&Vl[r * PADW + c] = make_float4(__uint_as_float(lx), __uint_as_float(ly),
                                                      __uint_as_float(lz), __uint_as_float(lw));
        }
        #pragma unroll
        for (int it = 0; it < 2; it++) {
            int idx = tid + it * 256;
            int r = idx >> 2, c16 = (idx & 3) * 16;
            uint4 mv = *(const uint4*)(mask + (size_t)(s0 + r) * T_LEN + j0 + c16);
            mor |= mv.x | mv.y | mv.z | mv.w;
        }
        int any_mask = __syncthreads_or((int)mor);

        // ---- S = Q K^T (3xTF32) ----
        float sc[8][4] = {};
        #pragma unroll
        for (int ks = 0; ks < 8; ks++) {
            int k0 = ks * 8;
            uint32_t ah[4], al[4];
            ah[0] = __float_as_uint(Qh[ rowA      * PADW + k0 + tg]);
            ah[1] = __float_as_uint(Qh[(rowA + 8) * PADW + k0 + tg]);
            ah[2] = __float_as_uint(Qh[ rowA      * PADW + k0 + tg + 4]);
            ah[3] = __float_as_uint(Qh[(rowA + 8) * PADW + k0 + tg + 4]);
            al[0] = __float_as_uint(Ql[ rowA      * PADW + k0 + tg]);
            al[1] = __float_as_uint(Ql[(rowA + 8) * PADW + k0 + tg]);
            al[2] = __float_as_uint(Ql[ rowA      * PADW + k0 + tg + 4]);
            al[3] = __float_as_uint(Ql[(rowA + 8) * PADW + k0 + tg + 4]);
            #pragma unroll
            for (int nt = 0; nt < 8; nt++) {
                int n = nt * 8 + g;
                uint32_t b0h = __float_as_uint(Kh[(k0 + tg)     * PADW + n]);
                uint32_t b1h = __float_as_uint(Kh[(k0 + tg + 4) * PADW + n]);
                uint32_t b0l = __float_as_uint(Kl[(k0 + tg)     * PADW + n]);
                uint32_t b1l = __float_as_uint(Kl[(k0 + tg + 4) * PADW + n]);
                mma_tf32(sc[nt], ah[0], ah[1], ah[2], ah[3], b0h, b1h);
                mma_tf32(sc[nt], ah[0], ah[1], ah[2], ah[3], b0l, b1l);
                mma_tf32(sc[nt], al[0], al[1], al[2], al[3], b0h, b1h);
            }
        }

        // ---- scale + (rare) mask ----
        #pragma unroll
        for (int nt = 0; nt < 8; nt++) {
            sc[nt][0] *= 0.125f; sc[nt][1] *= 0.125f;
            sc[nt][2] *= 0.125f; sc[nt][3] *= 0.125f;
        }
        if (any_mask) {
            int sg0 = s0 + rowA, sg1 = sg0 + 8;
            #pragma unroll
            for (int nt = 0; nt < 8; nt++) {
                int cg = j0 + nt * 8 + tg * 2;
                const unsigned char* m0p = mask + (size_t)sg0 * T_LEN + cg;
                const unsigned char* m1p = mask + (size_t)sg1 * T_LEN + cg;
                if (m0p[0]) sc[nt][0] = -INFINITY;
                if (m0p[1]) sc[nt][1] = -INFINITY;
                if (m1p[0]) sc[nt][2] = -INFINITY;
                if (m1p[1]) sc[nt][3] = -INFINITY;
            }
        }

        // ---- warp-local online softmax (rows g and g+8) ----
        float mx0 = -1e30f, mx1 = -1e30f;
        #pragma unroll
        for (int nt = 0; nt < 8; nt++) {
            mx0 = fmaxf(mx0, fmaxf(sc[nt][0], sc[nt][1]));
            mx1 = fmaxf(mx1, fmaxf(sc[nt][2], sc[nt][3]));
        }
        mx0 = fmaxf(mx0, __shfl_xor_sync(0xffffffffu, mx0, 1));
        mx0 = fmaxf(mx0, __shfl_xor_sync(0xffffffffu, mx0, 2));
        mx1 = fmaxf(mx1, __shfl_xor_sync(0xffffffffu, mx1, 1));
        mx1 = fmaxf(mx1, __shfl_xor_sync(0xffffffffu, mx1, 2));

        float mn0 = fmaxf(m0, mx0), mn1 = fmaxf(m1, mx1);
        float cr0 = __expf(m0 - mn0), cr1 = __expf(m1 - mn1);
        float ps0 = 0.f, ps1 = 0.f;
        #pragma unroll
        for (int nt = 0; nt < 8; nt++) {
            sc[nt][0] = __expf(sc[nt][0] - mn0);
            sc[nt][1] = __expf(sc[nt][1] - mn0);
            sc[nt][2] = __expf(sc[nt][2] - mn1);
            sc[nt][3] = __expf(sc[nt][3] - mn1);
            ps0 += sc[nt][0] + sc[nt][1];
            ps1 += sc[nt][2] + sc[nt][3];
        }
        ps0 += __shfl_xor_sync(0xffffffffu, ps0, 1);
        ps0 += __shfl_xor_sync(0xffffffffu, ps0, 2);
        ps1 += __shfl_xor_sync(0xffffffffu, ps1, 1);
        ps1 += __shfl_xor_sync(0xffffffffu, ps1, 2);
        l0 = l0 * cr0 + ps0; m0 = mn0;
        l1 = l1 * cr1 + ps1; m1 = mn1;
        #pragma unroll
        for (int nt = 0; nt < 8; nt++) {
            o[nt][0] *= cr0; o[nt][1] *= cr0;
            o[nt][2] *= cr1; o[nt][3] *= cr1;
        }

        // ---- stage P (warp-private rows) ----
        #pragma unroll
        for (int nt = 0; nt < 8; nt++) {
            int c = nt * 8 + tg * 2;
            *(float2*)&Ps[ rowA      * PADW + c] = make_float2(sc[nt][0], sc[nt][1]);
            *(float2*)&Ps[(rowA + 8) * PADW + c] = make_float2(sc[nt][2], sc[nt][3]);
        }
        __syncwarp();

        // ---- O += P V (3xTF32) ----
        #pragma unroll
        for (int ks = 0; ks < 8; ks++) {
            int k0 = ks * 8;
            uint32_t ah[4], al[4];
            split_tf32(Ps[ rowA      * PADW + k0 + tg],     ah[0], al[0]);
            split_tf32(Ps[(rowA + 8) * PADW + k0 + tg],     ah[1], al[1]);
            split_tf32(Ps[ rowA      * PADW + k0 + tg + 4], ah[2], al[2]);
            split_tf32(Ps[(rowA + 8) * PADW + k0 + tg + 4], ah[3], al[3]);
            #pragma unroll
            for (int nt = 0; nt < 8; nt++) {
                int n = nt * 8 + g;
                uint32_t b0h = __float_as_uint(Vh[(k0 + tg)     * PADW + n]);
                uint32_t b1h = __float_as_uint(Vh[(k0 + tg + 4) * PADW + n]);
                uint32_t b0l = __float_as_uint(Vl[(k0 + tg)     * PADW + n]);
                uint32_t b1l = __float_as_uint(Vl[(k0 + tg + 4) * PADW + n]);
                mma_tf32(o[nt], ah[0], ah[1], ah[2], ah[3], b0h, b1h);
                mma_tf32(o[nt], ah[0], ah[1], ah[2], ah[3], b0l, b1l);
                mma_tf32(o[nt], al[0], al[1], al[2], al[3], b0h, b1h);
            }
        }
    }

    // ---- epilogue: normalize + store (S,B,HD) ----
    float i0 = 1.f / l0, i1 = 1.f / l1;
    int sg0 = s0 + rowA, sg1 = sg0 + 8;
    #pragma unroll
    for (int nt = 0; nt < 8; nt++) {
        int d = nt * 8 + tg * 2;
        *(float2*)(g_AV + ((size_t)sg0 * BATCH + b) * HD + h * HDIM + d) =
            make_float2(o[nt][0] * i0, o[nt][1] * i0);
        *(float2*)(g_AV + ((size_t)sg1 * BATCH + b) * HD + h * HDIM + d) =
            make_float2(o[nt][2] * i1, o[nt][3] * i1);
    }
}

// ---------------------------------------------------------------------------
extern "C" void kernel_launch(void* const* d_in, const int* in_sizes, int n_in,
                              void* d_out, int out_size)
{
    const float* inputs = (const float*)d_in[0];
    const float* enc    = (const float*)d_in[2];
    const float* u      = (const float*)d_in[3];
    const unsigned char* mask = (const unsigned char*)d_in[5];
    const float* Wkv = (const float*)d_in[6];
    const float* bkv = (const float*)d_in[7];
    const float* Wq  = (const float*)d_in[8];
    const float* bq  = (const float*)d_in[9];
    const float* Wp  = (const float*)d_in[10];
    const float* bp  = (const float*)d_in[11];
    float* out = (float*)d_out;

    const int ASMEM = (2 * 128 + 2 * 64 + 2 * 64 + 128) * PADW * 4;  // 174080 B
    cudaFuncSetAttribute(attn_mma, cudaFuncAttributeMaxDynamicSharedMemorySize, ASMEM);

    dim3 blk(256);
    mma_gemm<0><<<dim3(16, 32), blk>>>(enc,    Wkv, bkv, nullptr, nullptr, 2 * HD);
    mma_gemm<1><<<dim3(8, 32),  blk>>>(inputs, Wq,  bq,  u,       nullptr, HD);
    attn_mma<<<dim3(S_LEN / 128, BATCH * HEADS), blk, ASMEM>>>(mask);
    mma_gemm<2><<<dim3(8, 32),  blk>>>(nullptr, Wp,  bp,  nullptr, out,    HD);
}